// round 14
// baseline (speedup 1.0000x reference)
#include <cuda_runtime.h>

#define Bz 64
#define Cz 128
#define Nz 4000
#define CLz 50
#define Hz 4
#define DHz 32
#define SCALORf 0.17677669529663687f

// f32x2 packed helpers
#define PACK2(dst,s)   asm("mov.b64 %0, {%1, %1};" : "=l"(dst) : "f"(s))
#define UNPACK2(lo,hi,v) asm("mov.b64 {%0, %1}, %2;" : "=f"(lo), "=f"(hi) : "l"(v))
#define FMA2(acc,a,b)  asm("fma.rn.f32x2 %0, %1, %2, %0;" : "+l"(acc) : "l"(a), "l"(b))

// ---------------- scratch ----------------
__device__ float g_mu[Bz*Cz], g_ivstd[Bz*Cz], g_vr[Bz*Cz], g_rs2[Cz];
__device__ float g_scale1[Bz*Cz], g_shift1[Bz*Cz], g_scale2[Bz*Cz], g_shift2[Bz*Cz];
__device__ float g_e1[Bz*CLz*Nz];
__device__ float g_S2[Bz*CLz*Nz];
__device__ float g_cxpart[Bz*8*Cz*CLz];
__device__ float g_zpart[Bz*8*CLz];
__device__ float g_cx[Bz*Cz*CLz];
__device__ float g_h1[Bz*Hz*4800];
__device__ float g_h1a[Hz*DHz], g_h1b[Hz*DHz];
__device__ float g_h2[Bz*Hz*1600];
__device__ float g_h2a[Hz*DHz], g_h2b[Hz*DHz];
__device__ float g_glob[Bz*Hz*DHz*CLz];
__device__ float g_resP[Bz*Cz*CLz];

// ---------------- per-(b,c) instance stats ----------------
__global__ void k_stats(const float* __restrict__ x){
    int bc = blockIdx.x, tid = threadIdx.x;
    const float* row = x + (size_t)bc*Nz;
    float s=0.f, ss=0.f;
    for(int i=tid;i<Nz;i+=256){ float v=row[i]; s+=v; ss=fmaf(v,v,ss); }
    __shared__ float s1[256], s2[256];
    s1[tid]=s; s2[tid]=ss; __syncthreads();
    for(int o=128;o>0;o>>=1){
        if(tid<o){ s1[tid]+=s1[tid+o]; s2[tid]+=s2[tid+o]; }
        __syncthreads();
    }
    if(tid==0){
        float mu = s1[0]/(float)Nz;
        float var = fmaxf(s2[0]/(float)Nz - mu*mu, 0.f);
        g_mu[bc]=mu; g_ivstd[bc]=rsqrtf(var+1e-3f); g_vr[bc]=var/(var+1e-3f);
    }
}

__global__ void k_chan(){
    int c=threadIdx.x;
    float s=0.f;
    for(int b=0;b<Bz;b++) s += g_vr[b*Cz+c];
    g_rs2[c] = rsqrtf(s/(float)Bz + 1e-5f);
}

__global__ void k_affine(const float* __restrict__ g1g, const float* __restrict__ g1b,
                         const float* __restrict__ g2g, const float* __restrict__ g2b){
    int bc = blockIdx.x*256+threadIdx.x;
    if(bc >= Bz*Cz) return;
    int c = bc & (Cz-1);
    float iv=g_ivstd[bc], m=g_mu[bc], rs=g_rs2[c];
    float a1=g1g[c]*rs*iv; g_scale1[bc]=a1; g_shift1[bc]=fmaf(-a1,m,g1b[c]);
    float a2=g2g[c]*rs*iv; g_scale2[bc]=a2; g_shift2[bc]=fmaf(-a2,m,g2b[c]);
}

// ---------------- embed: 4 cluster-groups(14 each) x 64 n-threads(4 each), FFMA2 ----------------
// grid (16 ntiles of 256, Bz, 2 groups), 256 threads.
__global__ void __launch_bounds__(256,2) k_embed(const float* __restrict__ x,
    const float* __restrict__ wg1, const float* __restrict__ bg1,
    const float* __restrict__ wg2, const float* __restrict__ bg2){
    extern __shared__ float sm[];
    float* Wt = sm;            // 128 rows x 64 slots (4 grps x 16, 14 used); reused as e2buf[56][128]
    float* r  = sm + Cz*64;    // 32 x 256
    __shared__ float bs[64], scl[Cz], shf[Cz], mx[256], iz[256];
    int b=blockIdx.y, g=blockIdx.z, tile=blockIdx.x, tid=threadIdx.x;
    const float* W   = g? wg2:wg1;
    const float* bgp = g? bg2:bg1;
    const float* sc  = (g? g_scale2:g_scale1)+b*Cz;
    const float* sf  = (g? g_shift2:g_shift1)+b*Cz;
    for(int i=tid;i<Cz*64;i+=256){
        int c=i>>6, s=i&63, gg=s>>4, k=s&15;
        int cl=14*gg+k;
        Wt[i] = (k<14 && cl<CLz)? W[cl*Cz+c] : 0.f;
    }
    if(tid<64){ int gg=tid>>4,k=tid&15,cl=14*gg+k; bs[tid]=(k<14&&cl<CLz)? bgp[cl]:0.f; }
    if(tid<Cz){ scl[tid]=sc[tid]; shf[tid]=sf[tid]; }
    __syncthreads();
    int nt=tid&63, grp=tid>>6;
    unsigned long long A[14][2];
    #pragma unroll
    for(int k=0;k<14;k++){ float bb=bs[grp*16+k]; PACK2(A[k][0],bb); A[k][1]=A[k][0]; }
    int n0=tile*256;
    for(int cc=0;cc<4;cc++){
        __syncthreads();
        #pragma unroll
        for(int t=0;t<8;t++){
            int e=(tid+256*t)*4, c=e>>8, nn=e&255;
            int gc=cc*32+c, n=n0+nn;
            float4 v = (n<Nz)? *(const float4*)&x[((size_t)(b*Cz+gc))*Nz+n]
                             : make_float4(0.f,0.f,0.f,0.f);
            float s=scl[gc], sh=shf[gc];
            float4 rr;
            rr.x=fmaxf(fmaf(s,v.x,sh),0.f); rr.y=fmaxf(fmaf(s,v.y,sh),0.f);
            rr.z=fmaxf(fmaf(s,v.z,sh),0.f); rr.w=fmaxf(fmaf(s,v.w,sh),0.f);
            *(float4*)&r[(c<<8)+nn]=rr;
        }
        __syncthreads();
        #pragma unroll 2
        for(int c=0;c<32;c++){
            ulonglong2 xv2 = *(const ulonglong2*)&r[(c<<8)+4*nt];
            const float* wr=&Wt[(((cc<<5)+c)<<6) + (grp<<4)];
            float4 w0=*(const float4*)wr;
            float4 w1=*(const float4*)(wr+4);
            float4 w2=*(const float4*)(wr+8);
            float4 w3=*(const float4*)(wr+12);
            unsigned long long wp;
            PACK2(wp,w0.x); FMA2(A[0][0],wp,xv2.x);  FMA2(A[0][1],wp,xv2.y);
            PACK2(wp,w0.y); FMA2(A[1][0],wp,xv2.x);  FMA2(A[1][1],wp,xv2.y);
            PACK2(wp,w0.z); FMA2(A[2][0],wp,xv2.x);  FMA2(A[2][1],wp,xv2.y);
            PACK2(wp,w0.w); FMA2(A[3][0],wp,xv2.x);  FMA2(A[3][1],wp,xv2.y);
            PACK2(wp,w1.x); FMA2(A[4][0],wp,xv2.x);  FMA2(A[4][1],wp,xv2.y);
            PACK2(wp,w1.y); FMA2(A[5][0],wp,xv2.x);  FMA2(A[5][1],wp,xv2.y);
            PACK2(wp,w1.z); FMA2(A[6][0],wp,xv2.x);  FMA2(A[6][1],wp,xv2.y);
            PACK2(wp,w1.w); FMA2(A[7][0],wp,xv2.x);  FMA2(A[7][1],wp,xv2.y);
            PACK2(wp,w2.x); FMA2(A[8][0],wp,xv2.x);  FMA2(A[8][1],wp,xv2.y);
            PACK2(wp,w2.y); FMA2(A[9][0],wp,xv2.x);  FMA2(A[9][1],wp,xv2.y);
            PACK2(wp,w2.z); FMA2(A[10][0],wp,xv2.x); FMA2(A[10][1],wp,xv2.y);
            PACK2(wp,w2.w); FMA2(A[11][0],wp,xv2.x); FMA2(A[11][1],wp,xv2.y);
            PACK2(wp,w3.x); FMA2(A[12][0],wp,xv2.x); FMA2(A[12][1],wp,xv2.y);
            PACK2(wp,w3.y); FMA2(A[13][0],wp,xv2.x); FMA2(A[13][1],wp,xv2.y);
        }
    }
    int n=n0+4*nt;
    if(g==0){
        if(n<Nz){
            #pragma unroll
            for(int k=0;k<14;k++){
                int cl=14*grp+k;
                if(cl<CLz) *(ulonglong2*)&g_e1[((size_t)(b*CLz+cl))*Nz+n]=make_ulonglong2(A[k][0],A[k][1]);
            }
        }
    } else {
        float* e2 = Wt;   // 56 x 128 fits in 128*64 region
        for(int h=0;h<2;h++){
            __syncthreads();
            if((nt>>5)==h){
                #pragma unroll
                for(int k=0;k<14;k++){
                    int cl=14*grp+k;
                    *(ulonglong2*)&e2[(cl<<7)+4*(nt&31)]=make_ulonglong2(A[k][0],A[k][1]);
                }
            }
            __syncthreads();
            if(tid<128){
                float m=-1e30f;
                for(int cl=0;cl<CLz;cl++) m=fmaxf(m,e2[(cl<<7)+tid]);
                float z=0.f;
                for(int cl=0;cl<CLz;cl++) z+=__expf(e2[(cl<<7)+tid]-m);
                mx[h*128+tid]=m; iz[h*128+tid]=1.f/z;
            }
        }
        __syncthreads();
        if(n<Nz){
            float4 m4=*(const float4*)&mx[4*nt];
            float4 i4=*(const float4*)&iz[4*nt];
            #pragma unroll
            for(int k=0;k<14;k++){
                int cl=14*grp+k;
                if(cl<CLz){
                    float ax,ay,az,aw;
                    UNPACK2(ax,ay,A[k][0]); UNPACK2(az,aw,A[k][1]);
                    float4 o;
                    o.x=__expf(ax-m4.x)*i4.x; o.y=__expf(ay-m4.y)*i4.y;
                    o.z=__expf(az-m4.z)*i4.z; o.w=__expf(aw-m4.w)*i4.w;
                    *(float4*)&g_S2[((size_t)(b*CLz+cl))*Nz+n]=o;
                }
            }
        }
    }
}

// ---------------- cluster_x = x @ exp(e1) (unnormalized) + per-cluster Z partials ----------------
__global__ void k_clusterx(const float* __restrict__ x){
    int chunk=blockIdx.x, b=blockIdx.y, tid=threadIdx.x;
    int n0c=chunk*500, nend=n0c+500;
    __shared__ float xs_t[32*132];
    __shared__ float ws[56*32];
    int cg=tid&31, clg=tid>>5;
    float a[7][4];
    #pragma unroll
    for(int k=0;k<7;k++){ a[k][0]=0.f;a[k][1]=0.f;a[k][2]=0.f;a[k][3]=0.f; }
    float zacc=0.f;
    for(int n0=n0c;n0<nend;n0+=32){
        __syncthreads();
        for(int i=tid;i<Cz*32;i+=256){
            int c=i>>5, nn=i&31, n=n0+nn;
            xs_t[nn*132+c] = (n<nend)? x[((size_t)b*Cz+c)*Nz+n] : 0.f;
        }
        for(int i=tid;i<56*32;i+=256){
            int cl=i>>5, nn=i&31, n=n0+nn;
            ws[i] = (cl<CLz && n<nend)? __expf(g_e1[((size_t)b*CLz+cl)*Nz+n]) : 0.f;
        }
        __syncthreads();
        if(tid<56){
            #pragma unroll 8
            for(int nn=0;nn<32;nn++) zacc += ws[(tid<<5)+nn];
        }
        #pragma unroll 4
        for(int nn=0;nn<32;nn++){
            float4 xv=*(const float4*)&xs_t[nn*132+4*cg];
            #pragma unroll
            for(int k=0;k<7;k++){
                float w=ws[((clg+8*k)<<5)+nn];
                a[k][0]=fmaf(w,xv.x,a[k][0]); a[k][1]=fmaf(w,xv.y,a[k][1]);
                a[k][2]=fmaf(w,xv.z,a[k][2]); a[k][3]=fmaf(w,xv.w,a[k][3]);
            }
        }
    }
    if(tid<CLz) g_zpart[((size_t)(b*8+chunk))*CLz + tid] = zacc;
    float* dst=g_cxpart+((size_t)(b*8+chunk))*(Cz*CLz);
    #pragma unroll
    for(int k=0;k<7;k++){
        int cl=clg+8*k;
        if(cl<CLz){
            #pragma unroll
            for(int q=0;q<4;q++) dst[(4*cg+q)*CLz+cl]=a[k][q];
        }
    }
}

__global__ void k_cxsum(){
    int i = blockIdx.x*256+threadIdx.x;
    if(i >= Bz*Cz*CLz) return;
    int b = i/(Cz*CLz), j = i%(Cz*CLz);
    int cl = j%CLz;
    float Z=0.f;
    #pragma unroll
    for(int c=0;c<8;c++) Z += g_zpart[((size_t)(b*8+c))*CLz + cl];
    float s=0.f;
    #pragma unroll
    for(int c=0;c<8;c++) s += g_cxpart[((size_t)(b*8+c))*(Cz*CLz) + j];
    g_cx[i]=s/Z;
}

// ---------------- local branch: q, knn top-9, conv1 raw ----------------
__global__ void k_local1(const float* __restrict__ qkv_w, const float* __restrict__ qkv_b,
                         const float* __restrict__ gc1_w, const float* __restrict__ gc1_b){
    int b=blockIdx.x, h=blockIdx.y, tid=threadIdx.x;
    __shared__ float xts[CLz*33];
    __shared__ float sqs[CLz];
    __shared__ int idxs[CLz*9];
    __shared__ float w1s[DHz*193];
    const float* cx=g_cx+(size_t)b*(Cz*CLz);
    for(int i=tid;i<DHz*CLz;i+=256){
        int o=i/CLz, cl=i%CLz;
        float acc=qkv_b[h*DHz+o];
        const float* wr=qkv_w+(h*DHz+o)*Cz;
        #pragma unroll 8
        for(int d=0;d<Cz;d++) acc=fmaf(wr[d],cx[d*CLz+cl],acc);
        xts[cl*33+o]=acc;
    }
    for(int i=tid;i<DHz*192;i+=256)
        w1s[(i/192)*193+(i%192)] = gc1_w[h*DHz*192+i];
    __syncthreads();
    if(tid<CLz){
        float s=0.f;
        for(int d=0;d<DHz;d++){ float v=xts[tid*33+d]; s=fmaf(v,v,s); }
        sqs[tid]=s;
    }
    __syncthreads();
    if(tid<CLz){
        float vals[9]; int inds[9];
        #pragma unroll
        for(int k=0;k<9;k++){ vals[k]=-1e30f; inds[k]=0; }
        for(int m=0;m<CLz;m++){
            float inner=0.f;
            for(int d=0;d<DHz;d++) inner=fmaf(xts[tid*33+d],xts[m*33+d],inner);
            float pd=2.f*inner-sqs[tid]-sqs[m];
            if(pd>vals[8]){
                int p=8;
                while(p>0&&pd>vals[p-1]){ vals[p]=vals[p-1]; inds[p]=inds[p-1]; p--; }
                vals[p]=pd; inds[p]=m;
            }
        }
        for(int k=0;k<9;k++) idxs[tid*9+k]=inds[k];
    }
    __syncthreads();
    for(int idx=tid; idx<4800; idx+=256){
        int n=idx/96, rj=idx%96, j=rj>>5, o=rj&31;
        float acc=gc1_b[h*DHz+o];
        const float* wo=w1s+o*193;
        int m0=idxs[n*9+3*j], m1=idxs[n*9+3*j+1], m2=idxs[n*9+3*j+2];
        #pragma unroll 8
        for(int i=0;i<DHz;i++){
            float c=xts[n*33+i];
            float d0=c-xts[m0*33+i], d1=c-xts[m1*33+i], d2=c-xts[m2*33+i];
            acc=fmaf(wo[i*3],c,acc); acc=fmaf(wo[i*3+1],c,acc); acc=fmaf(wo[i*3+2],c,acc);
            acc=fmaf(wo[(i+32)*3],d0,acc); acc=fmaf(wo[(i+32)*3+1],d1,acc); acc=fmaf(wo[(i+32)*3+2],d2,acc);
        }
        g_h1[((size_t)(b*Hz+h))*4800+idx]=acc;
    }
}

// ---------------- BN stats over (b,n,j) per (h,o) ----------------
__global__ void k_bn1(const float* __restrict__ gamma, const float* __restrict__ beta){
    int ho=blockIdx.x, tid=threadIdx.x, h=ho>>5, o=ho&31;
    __shared__ float s1[256], s2[256];
    float s=0.f, ss=0.f;
    for(int i=tid;i<Bz*150;i+=256){
        int bb=i/150, r=i%150;
        float v=g_h1[((size_t)(bb*Hz+h))*4800 + (r/3)*96 + (r%3)*32 + o];
        s+=v; ss=fmaf(v,v,ss);
    }
    s1[tid]=s; s2[tid]=ss; __syncthreads();
    for(int off=128;off>0;off>>=1){ if(tid<off){ s1[tid]+=s1[tid+off]; s2[tid]+=s2[tid+off]; } __syncthreads(); }
    if(tid==0){
        float mu=s1[0]/9600.f, var=fmaxf(s2[0]/9600.f-mu*mu,0.f);
        float aa=gamma[ho]*rsqrtf(var+1e-5f);
        g_h1a[ho]=aa; g_h1b[ho]=fmaf(-aa,mu,beta[ho]);
    }
}

// ---------------- conv2 raw ----------------
__global__ void k_conv2(const float* __restrict__ gc2_w, const float* __restrict__ gc2_b){
    int b=blockIdx.x, h=blockIdx.y, tid=threadIdx.x;
    __shared__ float hs[4800];
    __shared__ float w2s[DHz*97];
    for(int i=tid;i<4800;i+=256){
        int o=i&31, ho=h*DHz+o;
        hs[i]=fmaxf(fmaf(g_h1a[ho], g_h1[((size_t)(b*Hz+h))*4800+i], g_h1b[ho]),0.f);
    }
    for(int i=tid;i<DHz*96;i+=256) w2s[(i/96)*97+(i%96)]=gc2_w[h*DHz*96+i];
    __syncthreads();
    for(int idx=tid;idx<1600;idx+=256){
        int n=idx>>5, o=idx&31;
        float acc=gc2_b[h*DHz+o];
        const float* wo=w2s+o*97;
        #pragma unroll 8
        for(int i=0;i<DHz;i++){
            acc=fmaf(wo[i*3],  hs[n*96+i],   acc);
            acc=fmaf(wo[i*3+1],hs[n*96+32+i],acc);
            acc=fmaf(wo[i*3+2],hs[n*96+64+i],acc);
        }
        g_h2[((size_t)(b*Hz+h))*1600+idx]=acc;
    }
}

__global__ void k_bn2(const float* __restrict__ gamma, const float* __restrict__ beta){
    int ho=blockIdx.x, tid=threadIdx.x, h=ho>>5, o=ho&31;
    __shared__ float s1[256], s2[256];
    float s=0.f, ss=0.f;
    for(int i=tid;i<Bz*CLz;i+=256){
        int bb=i/CLz, n=i%CLz;
        float v=g_h2[((size_t)(bb*Hz+h))*1600+n*32+o];
        s+=v; ss=fmaf(v,v,ss);
    }
    s1[tid]=s; s2[tid]=ss; __syncthreads();
    for(int off=128;off>0;off>>=1){ if(tid<off){ s1[tid]+=s1[tid+off]; s2[tid]+=s2[tid+off]; } __syncthreads(); }
    if(tid==0){
        float mu=s1[0]/3200.f, var=fmaxf(s2[0]/3200.f-mu*mu,0.f);
        float aa=gamma[ho]*rsqrtf(var+1e-5f);
        g_h2a[ho]=aa; g_h2b[ho]=fmaf(-aa,mu,beta[ho]);
    }
}

// ---------------- global branch: tiny attention over 50 clusters ----------------
__global__ void k_glob(const float* __restrict__ qkv1_w, const float* __restrict__ qkv1_b){
    int b=blockIdx.x, h=blockIdx.y, tid=threadIdx.x; // 128 threads
    __shared__ float qs[96*CLz];
    __shared__ float att[CLz*CLz];
    const float* cx=g_cx+(size_t)b*Cz*CLz;
    for(int i=tid;i<96*CLz;i+=128){
        int o=i/CLz, cl=i%CLz;
        float acc=qkv1_b[h*96+o];
        const float* wr=qkv1_w+(h*96+o)*Cz;
        #pragma unroll 8
        for(int d=0;d<Cz;d++) acc=fmaf(wr[d],cx[d*CLz+cl],acc);
        qs[o*CLz+cl]=acc;
    }
    __syncthreads();
    if(tid<CLz){
        int n=tid;
        float m=-1e30f;
        for(int mm=0;mm<CLz;mm++){
            float s=0.f;
            for(int d=0;d<DHz;d++) s=fmaf(qs[d*CLz+n], qs[(DHz+d)*CLz+mm], s);
            s*=SCALORf;
            att[n*CLz+mm]=s; m=fmaxf(m,s);
        }
        float z=0.f;
        for(int mm=0;mm<CLz;mm++){ float e=__expf(att[n*CLz+mm]-m); att[n*CLz+mm]=e; z+=e; }
        float izv=1.f/z;
        for(int mm=0;mm<CLz;mm++) att[n*CLz+mm]*=izv;
    }
    __syncthreads();
    for(int i=tid;i<DHz*CLz;i+=128){
        int d=i/CLz, n=i%CLz;
        float s=0.f;
        for(int mm=0;mm<CLz;mm++) s=fmaf(att[n*CLz+mm], qs[(64+d)*CLz+mm], s);
        g_glob[((size_t)(b*Hz+h)*DHz+d)*CLz+n]=s;
    }
}

// ---------------- res = pres @ cat + b; resP = proj @ res ----------------
__global__ void k_res(const float* __restrict__ pres_w, const float* __restrict__ pres_b,
                      const float* __restrict__ proj_w){
    extern __shared__ float catS[];   // 256*50
    int b=blockIdx.x, tid=threadIdx.x;
    for(int i=tid;i<256*CLz;i+=256){
        int k=i/CLz, c=i%CLz, h=k>>6, r=k&63;
        float v;
        if(r<32){ int ho=h*32+r; v=fmaxf(fmaf(g_h2a[ho], g_h2[((size_t)(b*Hz+h))*1600 + c*32 + r], g_h2b[ho]),0.f); }
        else      v=g_glob[((size_t)(b*Hz+h)*DHz + (r-32))*CLz + c];
        catS[k*CLz+c]=v;
    }
    __syncthreads();
    int o=tid&127, half=tid>>7;
    float acc[25];
    #pragma unroll
    for(int q=0;q<25;q++) acc[q]=0.f;
    for(int k=0;k<256;k++){
        float w=pres_w[o*256+k];
        const float* cr=&catS[k*CLz+half*25];
        #pragma unroll
        for(int q=0;q<25;q++) acc[q]=fmaf(w,cr[q],acc[q]);
    }
    float pb=pres_b[o];
    __syncthreads();
    for(int q=0;q<25;q++) catS[o*CLz+half*25+q]=acc[q]+pb;  // resS overlays catS
    __syncthreads();
    float a2[25];
    #pragma unroll
    for(int q=0;q<25;q++) a2[q]=0.f;
    for(int d=0;d<Cz;d++){
        float w=proj_w[o*Cz+d];
        const float* rr=&catS[d*CLz+half*25];
        #pragma unroll
        for(int q=0;q<25;q++) a2[q]=fmaf(w,rr[q],a2[q]);
    }
    for(int q=0;q<25;q++) g_resP[((size_t)b*Cz+o)*CLz+half*25+q]=a2[q];
}

// ---------------- out = resP @ S2 + proj_b ----------------
__global__ void k_final(const float* __restrict__ proj_b, float* __restrict__ out){
    __shared__ float rp[CLz*132];
    __shared__ float ss[CLz*64];
    __shared__ float pbs[Cz];
    int tile=blockIdx.x, b=blockIdx.y, tid=threadIdx.x;
    int n0=tile*64;
    for(int i=tid;i<Cz*CLz;i+=256){
        int o=i/CLz, c=i%CLz;
        rp[c*132+o]=g_resP[(size_t)b*Cz*CLz+i];
    }
    for(int i=tid;i<CLz*64;i+=256){
        int c=i>>6, nn=i&63, n=n0+nn;
        ss[i]=(n<Nz)? g_S2[((size_t)b*CLz+c)*Nz+n] : 0.f;
    }
    for(int i=tid;i<Cz;i+=256) pbs[i]=proj_b[i];
    __syncthreads();
    int to=tid>>3, tn=tid&7;
    float a[4][8];
    #pragma unroll
    for(int oi=0;oi<4;oi++) for(int j=0;j<8;j++) a[oi][j]=0.f;
    #pragma unroll 2
    for(int c=0;c<CLz;c++){
        float4 rv=*(const float4*)&rp[c*132+4*to];
        #pragma unroll
        for(int j=0;j<8;j++){
            float sv=ss[(c<<6)+tn+8*j];
            a[0][j]=fmaf(rv.x,sv,a[0][j]);
            a[1][j]=fmaf(rv.y,sv,a[1][j]);
            a[2][j]=fmaf(rv.z,sv,a[2][j]);
            a[3][j]=fmaf(rv.w,sv,a[3][j]);
        }
    }
    #pragma unroll
    for(int oi=0;oi<4;oi++){
        int o=4*to+oi; float pb=pbs[o];
        for(int j=0;j<8;j++){
            int n=n0+tn+8*j;
            if(n<Nz) out[((size_t)b*Cz+o)*Nz+n]=a[oi][j]+pb;
        }
    }
}

extern "C" void kernel_launch(void* const* d_in, const int* in_sizes, int n_in,
                              void* d_out, int out_size){
    const float* x      =(const float*)d_in[0];
    const float* wg1    =(const float*)d_in[1];
    const float* bg1    =(const float*)d_in[2];
    const float* g1g    =(const float*)d_in[3];
    const float* g1b    =(const float*)d_in[4];
    const float* wg2    =(const float*)d_in[5];
    const float* bg2    =(const float*)d_in[6];
    const float* g2g    =(const float*)d_in[7];
    const float* g2b    =(const float*)d_in[8];
    const float* qkv_w  =(const float*)d_in[9];
    const float* qkv_b  =(const float*)d_in[10];
    const float* qkv1_w =(const float*)d_in[11];
    const float* qkv1_b =(const float*)d_in[12];
    const float* gc1_w  =(const float*)d_in[13];
    const float* gc1_b  =(const float*)d_in[14];
    const float* gc1_g  =(const float*)d_in[15];
    const float* gc1_be =(const float*)d_in[16];
    const float* gc2_w  =(const float*)d_in[17];
    const float* gc2_b  =(const float*)d_in[18];
    const float* gc2_g  =(const float*)d_in[19];
    const float* gc2_be =(const float*)d_in[20];
    const float* pres_w =(const float*)d_in[21];
    const float* pres_b =(const float*)d_in[22];
    const float* proj_w =(const float*)d_in[23];
    const float* proj_b =(const float*)d_in[24];
    float* out=(float*)d_out;

    int embed_smem = (Cz*64 + 32*256)*4;   // 65536 bytes
    cudaFuncSetAttribute(k_embed, cudaFuncAttributeMaxDynamicSharedMemorySize, embed_smem);
    cudaFuncSetAttribute(k_res,   cudaFuncAttributeMaxDynamicSharedMemorySize, 256*CLz*4);

    k_stats<<<Bz*Cz,256>>>(x);
    k_chan<<<1,Cz>>>();
    k_affine<<<(Bz*Cz+255)/256,256>>>(g1g,g1b,g2g,g2b);
    k_embed<<<dim3(16,Bz,2),256,embed_smem>>>(x,wg1,bg1,wg2,bg2);
    k_clusterx<<<dim3(8,Bz),256>>>(x);
    k_cxsum<<<(Bz*Cz*CLz+255)/256,256>>>();
    k_local1<<<dim3(Bz,Hz),256>>>(qkv_w,qkv_b,gc1_w,gc1_b);
    k_bn1<<<Hz*DHz,256>>>(gc1_g,gc1_be);
    k_conv2<<<dim3(Bz,Hz),256>>>(gc2_w,gc2_b);
    k_bn2<<<Hz*DHz,256>>>(gc2_g,gc2_be);
    k_glob<<<dim3(Bz,Hz),128>>>(qkv1_w,qkv1_b);
    k_res<<<Bz,256,256*CLz*4>>>(pres_w,pres_b,proj_w);
    k_final<<<dim3((Nz+63)/64,Bz),256>>>(proj_b,out);
}

// round 15
// speedup vs baseline: 1.5488x; 1.5488x over previous
#include <cuda_runtime.h>

#define Bz 64
#define Cz 128
#define Nz 4000
#define CLz 50
#define Hz 4
#define DHz 32
#define SCALORf 0.17677669529663687f

// f32x2 packed helpers
#define PACK2(dst,s)   asm("mov.b64 %0, {%1, %1};" : "=l"(dst) : "f"(s))
#define UNPACK2(lo,hi,v) asm("mov.b64 {%0, %1}, %2;" : "=f"(lo), "=f"(hi) : "l"(v))
#define FMA2(acc,a,b)  asm("fma.rn.f32x2 %0, %1, %2, %0;" : "+l"(acc) : "l"(a), "l"(b))

// ---------------- scratch ----------------
__device__ float g_mu[Bz*Cz], g_ivstd[Bz*Cz], g_vr[Bz*Cz], g_rs2[Cz];
__device__ float g_scale1[Bz*Cz], g_shift1[Bz*Cz], g_scale2[Bz*Cz], g_shift2[Bz*Cz];
__device__ float g_e1[Bz*CLz*Nz];
__device__ float g_S2[Bz*CLz*Nz];
__device__ float g_rmax[Bz*CLz], g_riz[Bz*CLz];
__device__ float g_cxpart[Bz*8*Cz*CLz];
__device__ float g_cx[Bz*Cz*CLz];
__device__ float g_h1[Bz*Hz*4800];
__device__ float g_h1a[Hz*DHz], g_h1b[Hz*DHz];
__device__ float g_h2[Bz*Hz*1600];
__device__ float g_h2a[Hz*DHz], g_h2b[Hz*DHz];
__device__ float g_glob[Bz*Hz*DHz*CLz];
__device__ float g_resP[Bz*Cz*CLz];

// ---------------- per-(b,c) instance stats ----------------
__global__ void k_stats(const float* __restrict__ x){
    int bc = blockIdx.x, tid = threadIdx.x;
    const float* row = x + (size_t)bc*Nz;
    float s=0.f, ss=0.f;
    for(int i=tid;i<Nz;i+=256){ float v=row[i]; s+=v; ss=fmaf(v,v,ss); }
    __shared__ float s1[256], s2[256];
    s1[tid]=s; s2[tid]=ss; __syncthreads();
    for(int o=128;o>0;o>>=1){
        if(tid<o){ s1[tid]+=s1[tid+o]; s2[tid]+=s2[tid+o]; }
        __syncthreads();
    }
    if(tid==0){
        float mu = s1[0]/(float)Nz;
        float var = fmaxf(s2[0]/(float)Nz - mu*mu, 0.f);
        g_mu[bc]=mu; g_ivstd[bc]=rsqrtf(var+1e-3f); g_vr[bc]=var/(var+1e-3f);
    }
}

__global__ void k_chan(){
    int c=threadIdx.x;
    float s=0.f;
    for(int b=0;b<Bz;b++) s += g_vr[b*Cz+c];
    g_rs2[c] = rsqrtf(s/(float)Bz + 1e-5f);
}

__global__ void k_affine(const float* __restrict__ g1g, const float* __restrict__ g1b,
                         const float* __restrict__ g2g, const float* __restrict__ g2b){
    int bc = blockIdx.x*256+threadIdx.x;
    if(bc >= Bz*Cz) return;
    int c = bc & (Cz-1);
    float iv=g_ivstd[bc], m=g_mu[bc], rs=g_rs2[c];
    float a1=g1g[c]*rs*iv; g_scale1[bc]=a1; g_shift1[bc]=fmaf(-a1,m,g1b[c]);
    float a2=g2g[c]*rs*iv; g_scale2[bc]=a2; g_shift2[bc]=fmaf(-a2,m,g2b[c]);
}

// ---------------- embed: 8 cluster-groups(7 each) x 32 n-threads(4 each), FFMA2 ----------------
__global__ void __launch_bounds__(256,3) k_embed(const float* __restrict__ x,
    const float* __restrict__ wg1, const float* __restrict__ bg1,
    const float* __restrict__ wg2, const float* __restrict__ bg2){
    extern __shared__ float sm[];
    float* Wt = sm;            // 128 rows x 64 slots; reused as e2buf[56][128]
    float* r  = sm + Cz*64;    // 32 x 128
    __shared__ float bs[64], scl[Cz], shf[Cz], mx[128], iz[128];
    int b=blockIdx.y, g=blockIdx.z, tile=blockIdx.x, tid=threadIdx.x;
    const float* W   = g? wg2:wg1;
    const float* bgp = g? bg2:bg1;
    const float* sc  = (g? g_scale2:g_scale1)+b*Cz;
    const float* sf  = (g? g_shift2:g_shift1)+b*Cz;
    for(int i=tid;i<Cz*64;i+=256){
        int c=i>>6, s=i&63, gg=s>>3, k=s&7;
        int cl=7*gg+k;
        Wt[i] = (k<7 && cl<CLz)? W[cl*Cz+c] : 0.f;
    }
    if(tid<64){ int gg=tid>>3,k=tid&7,cl=7*gg+k; bs[tid]=(k<7&&cl<CLz)? bgp[cl]:0.f; }
    if(tid<Cz){ scl[tid]=sc[tid]; shf[tid]=sf[tid]; }
    __syncthreads();
    int nt=tid&31, grp=tid>>5;
    unsigned long long A[7][2];
    #pragma unroll
    for(int k=0;k<7;k++){ float bb=bs[grp*8+k]; PACK2(A[k][0],bb); A[k][1]=A[k][0]; }
    int n0=tile*128;
    for(int cc=0;cc<4;cc++){
        __syncthreads();
        #pragma unroll
        for(int t=0;t<4;t++){
            int e=(tid+256*t)*4, c=e>>7, nn=e&127;
            int gc=cc*32+c, n=n0+nn;
            float4 v = (n<Nz)? *(const float4*)&x[((size_t)(b*Cz+gc))*Nz+n]
                             : make_float4(0.f,0.f,0.f,0.f);
            float s=scl[gc], sh=shf[gc];
            float4 rr;
            rr.x=fmaxf(fmaf(s,v.x,sh),0.f); rr.y=fmaxf(fmaf(s,v.y,sh),0.f);
            rr.z=fmaxf(fmaf(s,v.z,sh),0.f); rr.w=fmaxf(fmaf(s,v.w,sh),0.f);
            *(float4*)&r[(c<<7)+nn]=rr;
        }
        __syncthreads();
        #pragma unroll 2
        for(int c=0;c<32;c++){
            ulonglong2 xv2 = *(const ulonglong2*)&r[(c<<7)+4*nt];
            const float* wr=&Wt[(((cc<<5)+c)<<6) + (grp<<3)];
            float4 w0=*(const float4*)wr;
            float4 w1=*(const float4*)(wr+4);
            unsigned long long wp;
            PACK2(wp,w0.x); FMA2(A[0][0],wp,xv2.x); FMA2(A[0][1],wp,xv2.y);
            PACK2(wp,w0.y); FMA2(A[1][0],wp,xv2.x); FMA2(A[1][1],wp,xv2.y);
            PACK2(wp,w0.z); FMA2(A[2][0],wp,xv2.x); FMA2(A[2][1],wp,xv2.y);
            PACK2(wp,w0.w); FMA2(A[3][0],wp,xv2.x); FMA2(A[3][1],wp,xv2.y);
            PACK2(wp,w1.x); FMA2(A[4][0],wp,xv2.x); FMA2(A[4][1],wp,xv2.y);
            PACK2(wp,w1.y); FMA2(A[5][0],wp,xv2.x); FMA2(A[5][1],wp,xv2.y);
            PACK2(wp,w1.z); FMA2(A[6][0],wp,xv2.x); FMA2(A[6][1],wp,xv2.y);
        }
    }
    int n=n0+4*nt;
    if(g==0){
        if(n<Nz){
            #pragma unroll
            for(int k=0;k<7;k++){
                int cl=7*grp+k;
                if(cl<CLz) *(ulonglong2*)&g_e1[((size_t)(b*CLz+cl))*Nz+n]=make_ulonglong2(A[k][0],A[k][1]);
            }
        }
    } else {
        float* e2 = Wt;   // 56 x 128 fits in 128*64 region
        __syncthreads();  // compute loop done reading Wt
        #pragma unroll
        for(int k=0;k<7;k++){
            int cl=7*grp+k;
            *(ulonglong2*)&e2[(cl<<7)+4*nt]=make_ulonglong2(A[k][0],A[k][1]);
        }
        __syncthreads();
        if(tid<128){
            float m=-1e30f;
            for(int cl=0;cl<CLz;cl++) m=fmaxf(m,e2[(cl<<7)+tid]);
            float z=0.f;
            for(int cl=0;cl<CLz;cl++) z+=__expf(e2[(cl<<7)+tid]-m);
            mx[tid]=m; iz[tid]=1.f/z;
        }
        __syncthreads();
        if(n<Nz){
            float4 m4=*(const float4*)&mx[4*nt];
            float4 i4=*(const float4*)&iz[4*nt];
            #pragma unroll
            for(int k=0;k<7;k++){
                int cl=7*grp+k;
                if(cl<CLz){
                    float ax,ay,az,aw;
                    UNPACK2(ax,ay,A[k][0]); UNPACK2(az,aw,A[k][1]);
                    float4 o;
                    o.x=__expf(ax-m4.x)*i4.x; o.y=__expf(ay-m4.y)*i4.y;
                    o.z=__expf(az-m4.z)*i4.z; o.w=__expf(aw-m4.w)*i4.w;
                    *(float4*)&g_S2[((size_t)(b*CLz+cl))*Nz+n]=o;
                }
            }
        }
    }
}

// ---------------- softmax-over-n row stats for S1 ----------------
__global__ void k_rowsm(){
    int rdx = blockIdx.x, tid=threadIdx.x;
    const float* row = g_e1 + (size_t)rdx*Nz;
    __shared__ float sh[256];
    float m=-1e30f;
    for(int i=tid;i<Nz;i+=256) m=fmaxf(m,row[i]);
    sh[tid]=m; __syncthreads();
    for(int o=128;o>0;o>>=1){ if(tid<o) sh[tid]=fmaxf(sh[tid],sh[tid+o]); __syncthreads(); }
    m=sh[0]; __syncthreads();
    float s=0.f;
    for(int i=tid;i<Nz;i+=256) s+=__expf(row[i]-m);
    sh[tid]=s; __syncthreads();
    for(int o=128;o>0;o>>=1){ if(tid<o) sh[tid]+=sh[tid+o]; __syncthreads(); }
    if(tid==0){ g_rmax[rdx]=m; g_riz[rdx]=1.f/sh[0]; }
}

// ---------------- cluster_x = x @ S1 (S1 on the fly), padded to 56 clusters ----------------
__global__ void k_clusterx(const float* __restrict__ x){
    int chunk=blockIdx.x, b=blockIdx.y, tid=threadIdx.x;
    int n0c=chunk*500, nend=n0c+500;
    __shared__ float xs_t[32*132];
    __shared__ float ws[56*32];
    __shared__ float rm[CLz], rz[CLz];
    for(int i=tid;i<CLz;i+=256){ rm[i]=g_rmax[b*CLz+i]; rz[i]=g_riz[b*CLz+i]; }
    int cg=tid&31, clg=tid>>5;
    float a[7][4];
    #pragma unroll
    for(int k=0;k<7;k++){ a[k][0]=0.f;a[k][1]=0.f;a[k][2]=0.f;a[k][3]=0.f; }
    for(int n0=n0c;n0<nend;n0+=32){
        __syncthreads();
        for(int i=tid;i<Cz*32;i+=256){
            int c=i>>5, nn=i&31, n=n0+nn;
            xs_t[nn*132+c] = (n<nend)? x[((size_t)b*Cz+c)*Nz+n] : 0.f;
        }
        for(int i=tid;i<56*32;i+=256){
            int cl=i>>5, nn=i&31, n=n0+nn;
            ws[i] = (cl<CLz && n<nend)? __expf(g_e1[((size_t)b*CLz+cl)*Nz+n]-rm[cl])*rz[cl] : 0.f;
        }
        __syncthreads();
        #pragma unroll 4
        for(int nn=0;nn<32;nn++){
            float4 xv=*(const float4*)&xs_t[nn*132+4*cg];
            #pragma unroll
            for(int k=0;k<7;k++){
                float w=ws[((clg+8*k)<<5)+nn];
                a[k][0]=fmaf(w,xv.x,a[k][0]); a[k][1]=fmaf(w,xv.y,a[k][1]);
                a[k][2]=fmaf(w,xv.z,a[k][2]); a[k][3]=fmaf(w,xv.w,a[k][3]);
            }
        }
    }
    float* dst=g_cxpart+((size_t)(b*8+chunk))*(Cz*CLz);
    #pragma unroll
    for(int k=0;k<7;k++){
        int cl=clg+8*k;
        if(cl<CLz){
            #pragma unroll
            for(int q=0;q<4;q++) dst[(4*cg+q)*CLz+cl]=a[k][q];
        }
    }
}

__global__ void k_cxsum(){
    int i = blockIdx.x*256+threadIdx.x;
    if(i >= Bz*Cz*CLz) return;
    int b = i/(Cz*CLz), j = i%(Cz*CLz);
    float s=0.f;
    #pragma unroll
    for(int c=0;c<8;c++) s += g_cxpart[((size_t)(b*8+c))*(Cz*CLz) + j];
    g_cx[i]=s;
}

// ---------------- local branch: q, knn top-9, conv1 raw ----------------
__global__ void k_local1(const float* __restrict__ qkv_w, const float* __restrict__ qkv_b,
                         const float* __restrict__ gc1_w, const float* __restrict__ gc1_b){
    int b=blockIdx.x, h=blockIdx.y, tid=threadIdx.x;
    __shared__ float xts[CLz*33];
    __shared__ float sqs[CLz];
    __shared__ int idxs[CLz*9];
    __shared__ float w1s[DHz*193];
    const float* cx=g_cx+(size_t)b*(Cz*CLz);
    for(int i=tid;i<DHz*CLz;i+=256){
        int o=i/CLz, cl=i%CLz;
        float acc=qkv_b[h*DHz+o];
        const float* wr=qkv_w+(h*DHz+o)*Cz;
        #pragma unroll 8
        for(int d=0;d<Cz;d++) acc=fmaf(wr[d],cx[d*CLz+cl],acc);
        xts[cl*33+o]=acc;
    }
    for(int i=tid;i<DHz*192;i+=256)
        w1s[(i/192)*193+(i%192)] = gc1_w[h*DHz*192+i];
    __syncthreads();
    if(tid<CLz){
        float s=0.f;
        for(int d=0;d<DHz;d++){ float v=xts[tid*33+d]; s=fmaf(v,v,s); }
        sqs[tid]=s;
    }
    __syncthreads();
    if(tid<CLz){
        float vals[9]; int inds[9];
        #pragma unroll
        for(int k=0;k<9;k++){ vals[k]=-1e30f; inds[k]=0; }
        for(int m=0;m<CLz;m++){
            float inner=0.f;
            for(int d=0;d<DHz;d++) inner=fmaf(xts[tid*33+d],xts[m*33+d],inner);
            float pd=2.f*inner-sqs[tid]-sqs[m];
            if(pd>vals[8]){
                int p=8;
                while(p>0&&pd>vals[p-1]){ vals[p]=vals[p-1]; inds[p]=inds[p-1]; p--; }
                vals[p]=pd; inds[p]=m;
            }
        }
        for(int k=0;k<9;k++) idxs[tid*9+k]=inds[k];
    }
    __syncthreads();
    for(int idx=tid; idx<4800; idx+=256){
        int n=idx/96, rj=idx%96, j=rj>>5, o=rj&31;
        float acc=gc1_b[h*DHz+o];
        const float* wo=w1s+o*193;
        int m0=idxs[n*9+3*j], m1=idxs[n*9+3*j+1], m2=idxs[n*9+3*j+2];
        #pragma unroll 8
        for(int i=0;i<DHz;i++){
            float c=xts[n*33+i];
            float d0=c-xts[m0*33+i], d1=c-xts[m1*33+i], d2=c-xts[m2*33+i];
            acc=fmaf(wo[i*3],c,acc); acc=fmaf(wo[i*3+1],c,acc); acc=fmaf(wo[i*3+2],c,acc);
            acc=fmaf(wo[(i+32)*3],d0,acc); acc=fmaf(wo[(i+32)*3+1],d1,acc); acc=fmaf(wo[(i+32)*3+2],d2,acc);
        }
        g_h1[((size_t)(b*Hz+h))*4800+idx]=acc;
    }
}

// ---------------- BN stats over (b,n,j) per (h,o) ----------------
__global__ void k_bn1(const float* __restrict__ gamma, const float* __restrict__ beta){
    int ho=blockIdx.x, tid=threadIdx.x, h=ho>>5, o=ho&31;
    __shared__ float s1[256], s2[256];
    float s=0.f, ss=0.f;
    for(int i=tid;i<Bz*150;i+=256){
        int bb=i/150, r=i%150;
        float v=g_h1[((size_t)(bb*Hz+h))*4800 + (r/3)*96 + (r%3)*32 + o];
        s+=v; ss=fmaf(v,v,ss);
    }
    s1[tid]=s; s2[tid]=ss; __syncthreads();
    for(int off=128;off>0;off>>=1){ if(tid<off){ s1[tid]+=s1[tid+off]; s2[tid]+=s2[tid+off]; } __syncthreads(); }
    if(tid==0){
        float mu=s1[0]/9600.f, var=fmaxf(s2[0]/9600.f-mu*mu,0.f);
        float aa=gamma[ho]*rsqrtf(var+1e-5f);
        g_h1a[ho]=aa; g_h1b[ho]=fmaf(-aa,mu,beta[ho]);
    }
}

// ---------------- conv2 raw ----------------
__global__ void k_conv2(const float* __restrict__ gc2_w, const float* __restrict__ gc2_b){
    int b=blockIdx.x, h=blockIdx.y, tid=threadIdx.x;
    __shared__ float hs[4800];
    __shared__ float w2s[DHz*97];
    for(int i=tid;i<4800;i+=256){
        int o=i&31, ho=h*DHz+o;
        hs[i]=fmaxf(fmaf(g_h1a[ho], g_h1[((size_t)(b*Hz+h))*4800+i], g_h1b[ho]),0.f);
    }
    for(int i=tid;i<DHz*96;i+=256) w2s[(i/96)*97+(i%96)]=gc2_w[h*DHz*96+i];
    __syncthreads();
    for(int idx=tid;idx<1600;idx+=256){
        int n=idx>>5, o=idx&31;
        float acc=gc2_b[h*DHz+o];
        const float* wo=w2s+o*97;
        #pragma unroll 8
        for(int i=0;i<DHz;i++){
            acc=fmaf(wo[i*3],  hs[n*96+i],   acc);
            acc=fmaf(wo[i*3+1],hs[n*96+32+i],acc);
            acc=fmaf(wo[i*3+2],hs[n*96+64+i],acc);
        }
        g_h2[((size_t)(b*Hz+h))*1600+idx]=acc;
    }
}

__global__ void k_bn2(const float* __restrict__ gamma, const float* __restrict__ beta){
    int ho=blockIdx.x, tid=threadIdx.x, h=ho>>5, o=ho&31;
    __shared__ float s1[256], s2[256];
    float s=0.f, ss=0.f;
    for(int i=tid;i<Bz*CLz;i+=256){
        int bb=i/CLz, n=i%CLz;
        float v=g_h2[((size_t)(bb*Hz+h))*1600+n*32+o];
        s+=v; ss=fmaf(v,v,ss);
    }
    s1[tid]=s; s2[tid]=ss; __syncthreads();
    for(int off=128;off>0;off>>=1){ if(tid<off){ s1[tid]+=s1[tid+off]; s2[tid]+=s2[tid+off]; } __syncthreads(); }
    if(tid==0){
        float mu=s1[0]/3200.f, var=fmaxf(s2[0]/3200.f-mu*mu,0.f);
        float aa=gamma[ho]*rsqrtf(var+1e-5f);
        g_h2a[ho]=aa; g_h2b[ho]=fmaf(-aa,mu,beta[ho]);
    }
}

// ---------------- global branch: tiny attention over 50 clusters ----------------
__global__ void k_glob(const float* __restrict__ qkv1_w, const float* __restrict__ qkv1_b){
    int b=blockIdx.x, h=blockIdx.y, tid=threadIdx.x; // 128 threads
    __shared__ float qs[96*CLz];
    __shared__ float att[CLz*CLz];
    const float* cx=g_cx+(size_t)b*Cz*CLz;
    for(int i=tid;i<96*CLz;i+=128){
        int o=i/CLz, cl=i%CLz;
        float acc=qkv1_b[h*96+o];
        const float* wr=qkv1_w+(h*96+o)*Cz;
        #pragma unroll 8
        for(int d=0;d<Cz;d++) acc=fmaf(wr[d],cx[d*CLz+cl],acc);
        qs[o*CLz+cl]=acc;
    }
    __syncthreads();
    if(tid<CLz){
        int n=tid;
        float m=-1e30f;
        for(int mm=0;mm<CLz;mm++){
            float s=0.f;
            for(int d=0;d<DHz;d++) s=fmaf(qs[d*CLz+n], qs[(DHz+d)*CLz+mm], s);
            s*=SCALORf;
            att[n*CLz+mm]=s; m=fmaxf(m,s);
        }
        float z=0.f;
        for(int mm=0;mm<CLz;mm++){ float e=__expf(att[n*CLz+mm]-m); att[n*CLz+mm]=e; z+=e; }
        float izv=1.f/z;
        for(int mm=0;mm<CLz;mm++) att[n*CLz+mm]*=izv;
    }
    __syncthreads();
    for(int i=tid;i<DHz*CLz;i+=128){
        int d=i/CLz, n=i%CLz;
        float s=0.f;
        for(int mm=0;mm<CLz;mm++) s=fmaf(att[n*CLz+mm], qs[(64+d)*CLz+mm], s);
        g_glob[((size_t)(b*Hz+h)*DHz+d)*CLz+n]=s;
    }
}

// ---------------- res = pres @ cat + b; resP = proj @ res ----------------
__global__ void k_res(const float* __restrict__ pres_w, const float* __restrict__ pres_b,
                      const float* __restrict__ proj_w){
    extern __shared__ float catS[];   // 256*50
    int b=blockIdx.x, tid=threadIdx.x;
    for(int i=tid;i<256*CLz;i+=256){
        int k=i/CLz, c=i%CLz, h=k>>6, r=k&63;
        float v;
        if(r<32){ int ho=h*32+r; v=fmaxf(fmaf(g_h2a[ho], g_h2[((size_t)(b*Hz+h))*1600 + c*32 + r], g_h2b[ho]),0.f); }
        else      v=g_glob[((size_t)(b*Hz+h)*DHz + (r-32))*CLz + c];
        catS[k*CLz+c]=v;
    }
    __syncthreads();
    int o=tid&127, half=tid>>7;
    float acc[25];
    #pragma unroll
    for(int q=0;q<25;q++) acc[q]=0.f;
    for(int k=0;k<256;k++){
        float w=pres_w[o*256+k];
        const float* cr=&catS[k*CLz+half*25];
        #pragma unroll
        for(int q=0;q<25;q++) acc[q]=fmaf(w,cr[q],acc[q]);
    }
    float pb=pres_b[o];
    __syncthreads();
    for(int q=0;q<25;q++) catS[o*CLz+half*25+q]=acc[q]+pb;  // resS overlays catS
    __syncthreads();
    float a2[25];
    #pragma unroll
    for(int q=0;q<25;q++) a2[q]=0.f;
    for(int d=0;d<Cz;d++){
        float w=proj_w[o*Cz+d];
        const float* rr=&catS[d*CLz+half*25];
        #pragma unroll
        for(int q=0;q<25;q++) a2[q]=fmaf(w,rr[q],a2[q]);
    }
    for(int q=0;q<25;q++) g_resP[((size_t)b*Cz+o)*CLz+half*25+q]=a2[q];
}

// ---------------- out = resP @ S2 + proj_b ----------------
__global__ void k_final(const float* __restrict__ proj_b, float* __restrict__ out){
    __shared__ float rp[CLz*132];
    __shared__ float ss[CLz*64];
    __shared__ float pbs[Cz];
    int tile=blockIdx.x, b=blockIdx.y, tid=threadIdx.x;
    int n0=tile*64;
    for(int i=tid;i<Cz*CLz;i+=256){
        int o=i/CLz, c=i%CLz;
        rp[c*132+o]=g_resP[(size_t)b*Cz*CLz+i];
    }
    for(int i=tid;i<CLz*64;i+=256){
        int c=i>>6, nn=i&63, n=n0+nn;
        ss[i]=(n<Nz)? g_S2[((size_t)b*CLz+c)*Nz+n] : 0.f;
    }
    for(int i=tid;i<Cz;i+=256) pbs[i]=proj_b[i];
    __syncthreads();
    int to=tid>>3, tn=tid&7;
    float a[4][8];
    #pragma unroll
    for(int oi=0;oi<4;oi++) for(int j=0;j<8;j++) a[oi][j]=0.f;
    #pragma unroll 2
    for(int c=0;c<CLz;c++){
        float4 rv=*(const float4*)&rp[c*132+4*to];
        #pragma unroll
        for(int j=0;j<8;j++){
            float sv=ss[(c<<6)+tn+8*j];
            a[0][j]=fmaf(rv.x,sv,a[0][j]);
            a[1][j]=fmaf(rv.y,sv,a[1][j]);
            a[2][j]=fmaf(rv.z,sv,a[2][j]);
            a[3][j]=fmaf(rv.w,sv,a[3][j]);
        }
    }
    #pragma unroll
    for(int oi=0;oi<4;oi++){
        int o=4*to+oi; float pb=pbs[o];
        for(int j=0;j<8;j++){
            int n=n0+tn+8*j;
            if(n<Nz) out[((size_t)b*Cz+o)*Nz+n]=a[oi][j]+pb;
        }
    }
}

extern "C" void kernel_launch(void* const* d_in, const int* in_sizes, int n_in,
                              void* d_out, int out_size){
    const float* x      =(const float*)d_in[0];
    const float* wg1    =(const float*)d_in[1];
    const float* bg1    =(const float*)d_in[2];
    const float* g1g    =(const float*)d_in[3];
    const float* g1b    =(const float*)d_in[4];
    const float* wg2    =(const float*)d_in[5];
    const float* bg2    =(const float*)d_in[6];
    const float* g2g    =(const float*)d_in[7];
    const float* g2b    =(const float*)d_in[8];
    const float* qkv_w  =(const float*)d_in[9];
    const float* qkv_b  =(const float*)d_in[10];
    const float* qkv1_w =(const float*)d_in[11];
    const float* qkv1_b =(const float*)d_in[12];
    const float* gc1_w  =(const float*)d_in[13];
    const float* gc1_b  =(const float*)d_in[14];
    const float* gc1_g  =(const float*)d_in[15];
    const float* gc1_be =(const float*)d_in[16];
    const float* gc2_w  =(const float*)d_in[17];
    const float* gc2_b  =(const float*)d_in[18];
    const float* gc2_g  =(const float*)d_in[19];
    const float* gc2_be =(const float*)d_in[20];
    const float* pres_w =(const float*)d_in[21];
    const float* pres_b =(const float*)d_in[22];
    const float* proj_w =(const float*)d_in[23];
    const float* proj_b =(const float*)d_in[24];
    float* out=(float*)d_out;

    int embed_smem = (Cz*64 + 32*128)*4;   // 49152 bytes
    cudaFuncSetAttribute(k_embed, cudaFuncAttributeMaxDynamicSharedMemorySize, embed_smem);
    cudaFuncSetAttribute(k_res,   cudaFuncAttributeMaxDynamicSharedMemorySize, 256*CLz*4);

    k_stats<<<Bz*Cz,256>>>(x);
    k_chan<<<1,Cz>>>();
    k_affine<<<(Bz*Cz+255)/256,256>>>(g1g,g1b,g2g,g2b);
    k_embed<<<dim3(32,Bz,2),256,embed_smem>>>(x,wg1,bg1,wg2,bg2);
    k_rowsm<<<Bz*CLz,256>>>();
    k_clusterx<<<dim3(8,Bz),256>>>(x);
    k_cxsum<<<(Bz*Cz*CLz+255)/256,256>>>();
    k_local1<<<dim3(Bz,Hz),256>>>(qkv_w,qkv_b,gc1_w,gc1_b);
    k_bn1<<<Hz*DHz,256>>>(gc1_g,gc1_be);
    k_conv2<<<dim3(Bz,Hz),256>>>(gc2_w,gc2_b);
    k_bn2<<<Hz*DHz,256>>>(gc2_g,gc2_be);
    k_glob<<<dim3(Bz,Hz),128>>>(qkv1_w,qkv1_b);
    k_res<<<Bz,256,256*CLz*4>>>(pres_w,pres_b,proj_w);
    k_final<<<dim3((Nz+63)/64,Bz),256>>>(proj_b,out);
}

// round 16
// speedup vs baseline: 1.5637x; 1.0096x over previous
#include <cuda_runtime.h>

#define Bz 64
#define Cz 128
#define Nz 4000
#define CLz 50
#define Hz 4
#define DHz 32
#define SCALORf 0.17677669529663687f

// f32x2 packed helpers
#define PACK2(dst,s)   asm("mov.b64 %0, {%1, %1};" : "=l"(dst) : "f"(s))
#define UNPACK2(lo,hi,v) asm("mov.b64 {%0, %1}, %2;" : "=f"(lo), "=f"(hi) : "l"(v))
#define FMA2(acc,a,b)  asm("fma.rn.f32x2 %0, %1, %2, %0;" : "+l"(acc) : "l"(a), "l"(b))

// ---------------- scratch ----------------
__device__ float g_mu[Bz*Cz], g_ivstd[Bz*Cz], g_vr[Bz*Cz], g_rs2[Cz];
__device__ float g_scale1[Bz*Cz], g_shift1[Bz*Cz], g_scale2[Bz*Cz], g_shift2[Bz*Cz];
__device__ float g_e1[Bz*CLz*Nz];
__device__ float g_S2[Bz*CLz*Nz];
__device__ float g_tmax[Bz*CLz*32], g_tz[Bz*CLz*32];
__device__ float g_rmax[Bz*CLz], g_riz[Bz*CLz];
__device__ float g_cxpart[Bz*8*Cz*CLz];
__device__ float g_cx[Bz*Cz*CLz];
__device__ float g_h1[Bz*Hz*4800];
__device__ float g_h1a[Hz*DHz], g_h1b[Hz*DHz];
__device__ float g_h2[Bz*Hz*1600];
__device__ float g_h2a[Hz*DHz], g_h2b[Hz*DHz];
__device__ float g_glob[Bz*Hz*DHz*CLz];
__device__ float g_resP[Bz*Cz*CLz];

// ---------------- per-(b,c) instance stats ----------------
__global__ void k_stats(const float* __restrict__ x){
    int bc = blockIdx.x, tid = threadIdx.x;
    const float* row = x + (size_t)bc*Nz;
    float s=0.f, ss=0.f;
    for(int i=tid;i<Nz;i+=256){ float v=row[i]; s+=v; ss=fmaf(v,v,ss); }
    __shared__ float s1[256], s2[256];
    s1[tid]=s; s2[tid]=ss; __syncthreads();
    for(int o=128;o>0;o>>=1){
        if(tid<o){ s1[tid]+=s1[tid+o]; s2[tid]+=s2[tid+o]; }
        __syncthreads();
    }
    if(tid==0){
        float mu = s1[0]/(float)Nz;
        float var = fmaxf(s2[0]/(float)Nz - mu*mu, 0.f);
        g_mu[bc]=mu; g_ivstd[bc]=rsqrtf(var+1e-3f); g_vr[bc]=var/(var+1e-3f);
    }
}

__global__ void k_chan(){
    int c=threadIdx.x;
    float s=0.f;
    for(int b=0;b<Bz;b++) s += g_vr[b*Cz+c];
    g_rs2[c] = rsqrtf(s/(float)Bz + 1e-5f);
}

__global__ void k_affine(const float* __restrict__ g1g, const float* __restrict__ g1b,
                         const float* __restrict__ g2g, const float* __restrict__ g2b){
    int bc = blockIdx.x*256+threadIdx.x;
    if(bc >= Bz*Cz) return;
    int c = bc & (Cz-1);
    float iv=g_ivstd[bc], m=g_mu[bc], rs=g_rs2[c];
    float a1=g1g[c]*rs*iv; g_scale1[bc]=a1; g_shift1[bc]=fmaf(-a1,m,g1b[c]);
    float a2=g2g[c]*rs*iv; g_scale2[bc]=a2; g_shift2[bc]=fmaf(-a2,m,g2b[c]);
}

// ---------------- embed: 8 cluster-groups(7 each) x 32 n-threads(4 each), FFMA2 ----------------
// g==0 also emits per-tile softmax-over-n partials via warp reductions.
__global__ void __launch_bounds__(256,3) k_embed(const float* __restrict__ x,
    const float* __restrict__ wg1, const float* __restrict__ bg1,
    const float* __restrict__ wg2, const float* __restrict__ bg2){
    extern __shared__ float sm[];
    float* Wt = sm;            // 128 rows x 64 slots; reused as e2buf[56][128]
    float* r  = sm + Cz*64;    // 32 x 128
    __shared__ float bs[64], scl[Cz], shf[Cz], mx[128], iz[128];
    int b=blockIdx.y, g=blockIdx.z, tile=blockIdx.x, tid=threadIdx.x;
    const float* W   = g? wg2:wg1;
    const float* bgp = g? bg2:bg1;
    const float* sc  = (g? g_scale2:g_scale1)+b*Cz;
    const float* sf  = (g? g_shift2:g_shift1)+b*Cz;
    for(int i=tid;i<Cz*64;i+=256){
        int c=i>>6, s=i&63, gg=s>>3, k=s&7;
        int cl=7*gg+k;
        Wt[i] = (k<7 && cl<CLz)? W[cl*Cz+c] : 0.f;
    }
    if(tid<64){ int gg=tid>>3,k=tid&7,cl=7*gg+k; bs[tid]=(k<7&&cl<CLz)? bgp[cl]:0.f; }
    if(tid<Cz){ scl[tid]=sc[tid]; shf[tid]=sf[tid]; }
    __syncthreads();
    int nt=tid&31, grp=tid>>5;
    unsigned long long A[7][2];
    #pragma unroll
    for(int k=0;k<7;k++){ float bb=bs[grp*8+k]; PACK2(A[k][0],bb); A[k][1]=A[k][0]; }
    int n0=tile*128;
    for(int cc=0;cc<4;cc++){
        __syncthreads();
        #pragma unroll
        for(int t=0;t<4;t++){
            int e=(tid+256*t)*4, c=e>>7, nn=e&127;
            int gc=cc*32+c, n=n0+nn;
            float4 v = (n<Nz)? *(const float4*)&x[((size_t)(b*Cz+gc))*Nz+n]
                             : make_float4(0.f,0.f,0.f,0.f);
            float s=scl[gc], sh=shf[gc];
            float4 rr;
            rr.x=fmaxf(fmaf(s,v.x,sh),0.f); rr.y=fmaxf(fmaf(s,v.y,sh),0.f);
            rr.z=fmaxf(fmaf(s,v.z,sh),0.f); rr.w=fmaxf(fmaf(s,v.w,sh),0.f);
            *(float4*)&r[(c<<7)+nn]=rr;
        }
        __syncthreads();
        #pragma unroll 2
        for(int c=0;c<32;c++){
            ulonglong2 xv2 = *(const ulonglong2*)&r[(c<<7)+4*nt];
            const float* wr=&Wt[(((cc<<5)+c)<<6) + (grp<<3)];
            float4 w0=*(const float4*)wr;
            float4 w1=*(const float4*)(wr+4);
            unsigned long long wp;
            PACK2(wp,w0.x); FMA2(A[0][0],wp,xv2.x); FMA2(A[0][1],wp,xv2.y);
            PACK2(wp,w0.y); FMA2(A[1][0],wp,xv2.x); FMA2(A[1][1],wp,xv2.y);
            PACK2(wp,w0.z); FMA2(A[2][0],wp,xv2.x); FMA2(A[2][1],wp,xv2.y);
            PACK2(wp,w0.w); FMA2(A[3][0],wp,xv2.x); FMA2(A[3][1],wp,xv2.y);
            PACK2(wp,w1.x); FMA2(A[4][0],wp,xv2.x); FMA2(A[4][1],wp,xv2.y);
            PACK2(wp,w1.y); FMA2(A[5][0],wp,xv2.x); FMA2(A[5][1],wp,xv2.y);
            PACK2(wp,w1.z); FMA2(A[6][0],wp,xv2.x); FMA2(A[6][1],wp,xv2.y);
        }
    }
    int n=n0+4*nt;
    if(g==0){
        if(n<Nz){
            #pragma unroll
            for(int k=0;k<7;k++){
                int cl=7*grp+k;
                if(cl<CLz) *(ulonglong2*)&g_e1[((size_t)(b*CLz+cl))*Nz+n]=make_ulonglong2(A[k][0],A[k][1]);
            }
        }
        // per-tile softmax partials: warp owns the full 128-n slice of its 7 clusters
        #pragma unroll
        for(int k=0;k<7;k++){
            int cl=7*grp+k;
            float ax,ay,az,aw;
            UNPACK2(ax,ay,A[k][0]); UNPACK2(az,aw,A[k][1]);
            if(n>=Nz){ ax=-1e30f; ay=-1e30f; az=-1e30f; aw=-1e30f; }
            float m=fmaxf(fmaxf(ax,ay),fmaxf(az,aw));
            #pragma unroll
            for(int o=16;o>0;o>>=1) m=fmaxf(m,__shfl_xor_sync(0xffffffffu,m,o));
            float z=__expf(ax-m)+__expf(ay-m)+__expf(az-m)+__expf(aw-m);
            #pragma unroll
            for(int o=16;o>0;o>>=1) z+=__shfl_xor_sync(0xffffffffu,z,o);
            if(nt==0 && cl<CLz){
                g_tmax[((size_t)(b*CLz+cl))*32+tile]=m;
                g_tz  [((size_t)(b*CLz+cl))*32+tile]=z;
            }
        }
    } else {
        float* e2 = Wt;   // 56 x 128 fits in 128*64 region
        __syncthreads();  // compute loop done reading Wt
        #pragma unroll
        for(int k=0;k<7;k++){
            int cl=7*grp+k;
            *(ulonglong2*)&e2[(cl<<7)+4*nt]=make_ulonglong2(A[k][0],A[k][1]);
        }
        __syncthreads();
        if(tid<128){
            float m=-1e30f;
            for(int cl=0;cl<CLz;cl++) m=fmaxf(m,e2[(cl<<7)+tid]);
            float z=0.f;
            for(int cl=0;cl<CLz;cl++) z+=__expf(e2[(cl<<7)+tid]-m);
            mx[tid]=m; iz[tid]=1.f/z;
        }
        __syncthreads();
        if(n<Nz){
            float4 m4=*(const float4*)&mx[4*nt];
            float4 i4=*(const float4*)&iz[4*nt];
            #pragma unroll
            for(int k=0;k<7;k++){
                int cl=7*grp+k;
                if(cl<CLz){
                    float ax,ay,az,aw;
                    UNPACK2(ax,ay,A[k][0]); UNPACK2(az,aw,A[k][1]);
                    float4 o;
                    o.x=__expf(ax-m4.x)*i4.x; o.y=__expf(ay-m4.y)*i4.y;
                    o.z=__expf(az-m4.z)*i4.z; o.w=__expf(aw-m4.w)*i4.w;
                    *(float4*)&g_S2[((size_t)(b*CLz+cl))*Nz+n]=o;
                }
            }
        }
    }
}

// ---------------- combine per-tile partials -> row max / 1/Z ----------------
__global__ void k_rowred(){
    int i = blockIdx.x*256+threadIdx.x;
    if(i>=Bz*CLz) return;
    const float* tm=&g_tmax[(size_t)i*32];
    const float* tz=&g_tz[(size_t)i*32];
    float M=-1e30f;
    #pragma unroll 8
    for(int t=0;t<32;t++) M=fmaxf(M,tm[t]);
    float Z=0.f;
    #pragma unroll 8
    for(int t=0;t<32;t++) Z=fmaf(__expf(tm[t]-M),tz[t],Z);
    g_rmax[i]=M; g_riz[i]=1.f/Z;
}

// ---------------- cluster_x = x @ S1 (S1 on the fly), padded to 56 clusters ----------------
__global__ void k_clusterx(const float* __restrict__ x){
    int chunk=blockIdx.x, b=blockIdx.y, tid=threadIdx.x;
    int n0c=chunk*500, nend=n0c+500;
    __shared__ float xs_t[32*132];
    __shared__ float ws[56*32];
    __shared__ float rm[CLz], rz[CLz];
    for(int i=tid;i<CLz;i+=256){ rm[i]=g_rmax[b*CLz+i]; rz[i]=g_riz[b*CLz+i]; }
    int cg=tid&31, clg=tid>>5;
    float a[7][4];
    #pragma unroll
    for(int k=0;k<7;k++){ a[k][0]=0.f;a[k][1]=0.f;a[k][2]=0.f;a[k][3]=0.f; }
    for(int n0=n0c;n0<nend;n0+=32){
        __syncthreads();
        for(int i=tid;i<Cz*32;i+=256){
            int c=i>>5, nn=i&31, n=n0+nn;
            xs_t[nn*132+c] = (n<nend)? x[((size_t)b*Cz+c)*Nz+n] : 0.f;
        }
        for(int i=tid;i<56*32;i+=256){
            int cl=i>>5, nn=i&31, n=n0+nn;
            ws[i] = (cl<CLz && n<nend)? __expf(g_e1[((size_t)b*CLz+cl)*Nz+n]-rm[cl])*rz[cl] : 0.f;
        }
        __syncthreads();
        #pragma unroll 4
        for(int nn=0;nn<32;nn++){
            float4 xv=*(const float4*)&xs_t[nn*132+4*cg];
            #pragma unroll
            for(int k=0;k<7;k++){
                float w=ws[((clg+8*k)<<5)+nn];
                a[k][0]=fmaf(w,xv.x,a[k][0]); a[k][1]=fmaf(w,xv.y,a[k][1]);
                a[k][2]=fmaf(w,xv.z,a[k][2]); a[k][3]=fmaf(w,xv.w,a[k][3]);
            }
        }
    }
    float* dst=g_cxpart+((size_t)(b*8+chunk))*(Cz*CLz);
    #pragma unroll
    for(int k=0;k<7;k++){
        int cl=clg+8*k;
        if(cl<CLz){
            #pragma unroll
            for(int q=0;q<4;q++) dst[(4*cg+q)*CLz+cl]=a[k][q];
        }
    }
}

__global__ void k_cxsum(){
    int i = blockIdx.x*256+threadIdx.x;
    if(i >= Bz*Cz*CLz) return;
    int b = i/(Cz*CLz), j = i%(Cz*CLz);
    float s=0.f;
    #pragma unroll
    for(int c=0;c<8;c++) s += g_cxpart[((size_t)(b*8+c))*(Cz*CLz) + j];
    g_cx[i]=s;
}

// ---------------- local branch: q, knn top-9, conv1 raw ----------------
__global__ void k_local1(const float* __restrict__ qkv_w, const float* __restrict__ qkv_b,
                         const float* __restrict__ gc1_w, const float* __restrict__ gc1_b){
    int b=blockIdx.x, h=blockIdx.y, tid=threadIdx.x;
    __shared__ float xts[CLz*33];
    __shared__ float sqs[CLz];
    __shared__ int idxs[CLz*9];
    __shared__ float w1s[DHz*193];
    const float* cx=g_cx+(size_t)b*(Cz*CLz);
    for(int i=tid;i<DHz*CLz;i+=256){
        int o=i/CLz, cl=i%CLz;
        float acc=qkv_b[h*DHz+o];
        const float* wr=qkv_w+(h*DHz+o)*Cz;
        #pragma unroll 8
        for(int d=0;d<Cz;d++) acc=fmaf(wr[d],cx[d*CLz+cl],acc);
        xts[cl*33+o]=acc;
    }
    for(int i=tid;i<DHz*192;i+=256)
        w1s[(i/192)*193+(i%192)] = gc1_w[h*DHz*192+i];
    __syncthreads();
    if(tid<CLz){
        float s=0.f;
        for(int d=0;d<DHz;d++){ float v=xts[tid*33+d]; s=fmaf(v,v,s); }
        sqs[tid]=s;
    }
    __syncthreads();
    if(tid<CLz){
        float vals[9]; int inds[9];
        #pragma unroll
        for(int k=0;k<9;k++){ vals[k]=-1e30f; inds[k]=0; }
        for(int m=0;m<CLz;m++){
            float inner=0.f;
            for(int d=0;d<DHz;d++) inner=fmaf(xts[tid*33+d],xts[m*33+d],inner);
            float pd=2.f*inner-sqs[tid]-sqs[m];
            if(pd>vals[8]){
                int p=8;
                while(p>0&&pd>vals[p-1]){ vals[p]=vals[p-1]; inds[p]=inds[p-1]; p--; }
                vals[p]=pd; inds[p]=m;
            }
        }
        for(int k=0;k<9;k++) idxs[tid*9+k]=inds[k];
    }
    __syncthreads();
    for(int idx=tid; idx<4800; idx+=256){
        int n=idx/96, rj=idx%96, j=rj>>5, o=rj&31;
        float acc=gc1_b[h*DHz+o];
        const float* wo=w1s+o*193;
        int m0=idxs[n*9+3*j], m1=idxs[n*9+3*j+1], m2=idxs[n*9+3*j+2];
        #pragma unroll 8
        for(int i=0;i<DHz;i++){
            float c=xts[n*33+i];
            float d0=c-xts[m0*33+i], d1=c-xts[m1*33+i], d2=c-xts[m2*33+i];
            acc=fmaf(wo[i*3],c,acc); acc=fmaf(wo[i*3+1],c,acc); acc=fmaf(wo[i*3+2],c,acc);
            acc=fmaf(wo[(i+32)*3],d0,acc); acc=fmaf(wo[(i+32)*3+1],d1,acc); acc=fmaf(wo[(i+32)*3+2],d2,acc);
        }
        g_h1[((size_t)(b*Hz+h))*4800+idx]=acc;
    }
}

// ---------------- BN stats over (b,n,j) per (h,o) ----------------
__global__ void k_bn1(const float* __restrict__ gamma, const float* __restrict__ beta){
    int ho=blockIdx.x, tid=threadIdx.x, h=ho>>5, o=ho&31;
    __shared__ float s1[256], s2[256];
    float s=0.f, ss=0.f;
    for(int i=tid;i<Bz*150;i+=256){
        int bb=i/150, r=i%150;
        float v=g_h1[((size_t)(bb*Hz+h))*4800 + (r/3)*96 + (r%3)*32 + o];
        s+=v; ss=fmaf(v,v,ss);
    }
    s1[tid]=s; s2[tid]=ss; __syncthreads();
    for(int off=128;off>0;off>>=1){ if(tid<off){ s1[tid]+=s1[tid+off]; s2[tid]+=s2[tid+off]; } __syncthreads(); }
    if(tid==0){
        float mu=s1[0]/9600.f, var=fmaxf(s2[0]/9600.f-mu*mu,0.f);
        float aa=gamma[ho]*rsqrtf(var+1e-5f);
        g_h1a[ho]=aa; g_h1b[ho]=fmaf(-aa,mu,beta[ho]);
    }
}

// ---------------- conv2 raw ----------------
__global__ void k_conv2(const float* __restrict__ gc2_w, const float* __restrict__ gc2_b){
    int b=blockIdx.x, h=blockIdx.y, tid=threadIdx.x;
    __shared__ float hs[4800];
    __shared__ float w2s[DHz*97];
    for(int i=tid;i<4800;i+=256){
        int o=i&31, ho=h*DHz+o;
        hs[i]=fmaxf(fmaf(g_h1a[ho], g_h1[((size_t)(b*Hz+h))*4800+i], g_h1b[ho]),0.f);
    }
    for(int i=tid;i<DHz*96;i+=256) w2s[(i/96)*97+(i%96)]=gc2_w[h*DHz*96+i];
    __syncthreads();
    for(int idx=tid;idx<1600;idx+=256){
        int n=idx>>5, o=idx&31;
        float acc=gc2_b[h*DHz+o];
        const float* wo=w2s+o*97;
        #pragma unroll 8
        for(int i=0;i<DHz;i++){
            acc=fmaf(wo[i*3],  hs[n*96+i],   acc);
            acc=fmaf(wo[i*3+1],hs[n*96+32+i],acc);
            acc=fmaf(wo[i*3+2],hs[n*96+64+i],acc);
        }
        g_h2[((size_t)(b*Hz+h))*1600+idx]=acc;
    }
}

__global__ void k_bn2(const float* __restrict__ gamma, const float* __restrict__ beta){
    int ho=blockIdx.x, tid=threadIdx.x, h=ho>>5, o=ho&31;
    __shared__ float s1[256], s2[256];
    float s=0.f, ss=0.f;
    for(int i=tid;i<Bz*CLz;i+=256){
        int bb=i/CLz, n=i%CLz;
        float v=g_h2[((size_t)(bb*Hz+h))*1600+n*32+o];
        s+=v; ss=fmaf(v,v,ss);
    }
    s1[tid]=s; s2[tid]=ss; __syncthreads();
    for(int off=128;off>0;off>>=1){ if(tid<off){ s1[tid]+=s1[tid+off]; s2[tid]+=s2[tid+off]; } __syncthreads(); }
    if(tid==0){
        float mu=s1[0]/3200.f, var=fmaxf(s2[0]/3200.f-mu*mu,0.f);
        float aa=gamma[ho]*rsqrtf(var+1e-5f);
        g_h2a[ho]=aa; g_h2b[ho]=fmaf(-aa,mu,beta[ho]);
    }
}

// ---------------- global branch: tiny attention over 50 clusters ----------------
__global__ void k_glob(const float* __restrict__ qkv1_w, const float* __restrict__ qkv1_b){
    int b=blockIdx.x, h=blockIdx.y, tid=threadIdx.x; // 128 threads
    __shared__ float qs[96*CLz];
    __shared__ float att[CLz*CLz];
    const float* cx=g_cx+(size_t)b*Cz*CLz;
    for(int i=tid;i<96*CLz;i+=128){
        int o=i/CLz, cl=i%CLz;
        float acc=qkv1_b[h*96+o];
        const float* wr=qkv1_w+(h*96+o)*Cz;
        #pragma unroll 8
        for(int d=0;d<Cz;d++) acc=fmaf(wr[d],cx[d*CLz+cl],acc);
        qs[o*CLz+cl]=acc;
    }
    __syncthreads();
    if(tid<CLz){
        int n=tid;
        float m=-1e30f;
        for(int mm=0;mm<CLz;mm++){
            float s=0.f;
            for(int d=0;d<DHz;d++) s=fmaf(qs[d*CLz+n], qs[(DHz+d)*CLz+mm], s);
            s*=SCALORf;
            att[n*CLz+mm]=s; m=fmaxf(m,s);
        }
        float z=0.f;
        for(int mm=0;mm<CLz;mm++){ float e=__expf(att[n*CLz+mm]-m); att[n*CLz+mm]=e; z+=e; }
        float izv=1.f/z;
        for(int mm=0;mm<CLz;mm++) att[n*CLz+mm]*=izv;
    }
    __syncthreads();
    for(int i=tid;i<DHz*CLz;i+=128){
        int d=i/CLz, n=i%CLz;
        float s=0.f;
        for(int mm=0;mm<CLz;mm++) s=fmaf(att[n*CLz+mm], qs[(64+d)*CLz+mm], s);
        g_glob[((size_t)(b*Hz+h)*DHz+d)*CLz+n]=s;
    }
}

// ---------------- res = pres @ cat + b; resP = proj @ res ----------------
__global__ void k_res(const float* __restrict__ pres_w, const float* __restrict__ pres_b,
                      const float* __restrict__ proj_w){
    extern __shared__ float catS[];   // 256*50
    int b=blockIdx.x, tid=threadIdx.x;
    for(int i=tid;i<256*CLz;i+=256){
        int k=i/CLz, c=i%CLz, h=k>>6, r=k&63;
        float v;
        if(r<32){ int ho=h*32+r; v=fmaxf(fmaf(g_h2a[ho], g_h2[((size_t)(b*Hz+h))*1600 + c*32 + r], g_h2b[ho]),0.f); }
        else      v=g_glob[((size_t)(b*Hz+h)*DHz + (r-32))*CLz + c];
        catS[k*CLz+c]=v;
    }
    __syncthreads();
    int o=tid&127, half=tid>>7;
    float acc[25];
    #pragma unroll
    for(int q=0;q<25;q++) acc[q]=0.f;
    for(int k=0;k<256;k++){
        float w=pres_w[o*256+k];
        const float* cr=&catS[k*CLz+half*25];
        #pragma unroll
        for(int q=0;q<25;q++) acc[q]=fmaf(w,cr[q],acc[q]);
    }
    float pb=pres_b[o];
    __syncthreads();
    for(int q=0;q<25;q++) catS[o*CLz+half*25+q]=acc[q]+pb;  // resS overlays catS
    __syncthreads();
    float a2[25];
    #pragma unroll
    for(int q=0;q<25;q++) a2[q]=0.f;
    for(int d=0;d<Cz;d++){
        float w=proj_w[o*Cz+d];
        const float* rr=&catS[d*CLz+half*25];
        #pragma unroll
        for(int q=0;q<25;q++) a2[q]=fmaf(w,rr[q],a2[q]);
    }
    for(int q=0;q<25;q++) g_resP[((size_t)b*Cz+o)*CLz+half*25+q]=a2[q];
}

// ---------------- out = resP @ S2 + proj_b ----------------
__global__ void k_final(const float* __restrict__ proj_b, float* __restrict__ out){
    __shared__ float rp[CLz*132];
    __shared__ float ss[CLz*64];
    __shared__ float pbs[Cz];
    int tile=blockIdx.x, b=blockIdx.y, tid=threadIdx.x;
    int n0=tile*64;
    for(int i=tid;i<Cz*CLz;i+=256){
        int o=i/CLz, c=i%CLz;
        rp[c*132+o]=g_resP[(size_t)b*Cz*CLz+i];
    }
    for(int i=tid;i<CLz*64;i+=256){
        int c=i>>6, nn=i&63, n=n0+nn;
        ss[i]=(n<Nz)? g_S2[((size_t)b*CLz+c)*Nz+n] : 0.f;
    }
    for(int i=tid;i<Cz;i+=256) pbs[i]=proj_b[i];
    __syncthreads();
    int to=tid>>3, tn=tid&7;
    float a[4][8];
    #pragma unroll
    for(int oi=0;oi<4;oi++) for(int j=0;j<8;j++) a[oi][j]=0.f;
    #pragma unroll 2
    for(int c=0;c<CLz;c++){
        float4 rv=*(const float4*)&rp[c*132+4*to];
        #pragma unroll
        for(int j=0;j<8;j++){
            float sv=ss[(c<<6)+tn+8*j];
            a[0][j]=fmaf(rv.x,sv,a[0][j]);
            a[1][j]=fmaf(rv.y,sv,a[1][j]);
            a[2][j]=fmaf(rv.z,sv,a[2][j]);
            a[3][j]=fmaf(rv.w,sv,a[3][j]);
        }
    }
    #pragma unroll
    for(int oi=0;oi<4;oi++){
        int o=4*to+oi; float pb=pbs[o];
        for(int j=0;j<8;j++){
            int n=n0+tn+8*j;
            if(n<Nz) out[((size_t)b*Cz+o)*Nz+n]=a[oi][j]+pb;
        }
    }
}

extern "C" void kernel_launch(void* const* d_in, const int* in_sizes, int n_in,
                              void* d_out, int out_size){
    const float* x      =(const float*)d_in[0];
    const float* wg1    =(const float*)d_in[1];
    const float* bg1    =(const float*)d_in[2];
    const float* g1g    =(const float*)d_in[3];
    const float* g1b    =(const float*)d_in[4];
    const float* wg2    =(const float*)d_in[5];
    const float* bg2    =(const float*)d_in[6];
    const float* g2g    =(const float*)d_in[7];
    const float* g2b    =(const float*)d_in[8];
    const float* qkv_w  =(const float*)d_in[9];
    const float* qkv_b  =(const float*)d_in[10];
    const float* qkv1_w =(const float*)d_in[11];
    const float* qkv1_b =(const float*)d_in[12];
    const float* gc1_w  =(const float*)d_in[13];
    const float* gc1_b  =(const float*)d_in[14];
    const float* gc1_g  =(const float*)d_in[15];
    const float* gc1_be =(const float*)d_in[16];
    const float* gc2_w  =(const float*)d_in[17];
    const float* gc2_b  =(const float*)d_in[18];
    const float* gc2_g  =(const float*)d_in[19];
    const float* gc2_be =(const float*)d_in[20];
    const float* pres_w =(const float*)d_in[21];
    const float* pres_b =(const float*)d_in[22];
    const float* proj_w =(const float*)d_in[23];
    const float* proj_b =(const float*)d_in[24];
    float* out=(float*)d_out;

    int embed_smem = (Cz*64 + 32*128)*4;   // 49152 bytes
    cudaFuncSetAttribute(k_embed, cudaFuncAttributeMaxDynamicSharedMemorySize, embed_smem);
    cudaFuncSetAttribute(k_res,   cudaFuncAttributeMaxDynamicSharedMemorySize, 256*CLz*4);

    k_stats<<<Bz*Cz,256>>>(x);
    k_chan<<<1,Cz>>>();
    k_affine<<<(Bz*Cz+255)/256,256>>>(g1g,g1b,g2g,g2b);
    k_embed<<<dim3(32,Bz,2),256,embed_smem>>>(x,wg1,bg1,wg2,bg2);
    k_rowred<<<(Bz*CLz+255)/256,256>>>();
    k_clusterx<<<dim3(8,Bz),256>>>(x);
    k_cxsum<<<(Bz*Cz*CLz+255)/256,256>>>();
    k_local1<<<dim3(Bz,Hz),256>>>(qkv_w,qkv_b,gc1_w,gc1_b);
    k_bn1<<<Hz*DHz,256>>>(gc1_g,gc1_be);
    k_conv2<<<dim3(Bz,Hz),256>>>(gc2_w,gc2_b);
    k_bn2<<<Hz*DHz,256>>>(gc2_g,gc2_be);
    k_glob<<<dim3(Bz,Hz),128>>>(qkv1_w,qkv1_b);
    k_res<<<Bz,256,256*CLz*4>>>(pres_w,pres_b,proj_w);
    k_final<<<dim3((Nz+63)/64,Bz),256>>>(proj_b,out);
}